// round 13
// baseline (speedup 1.0000x reference)
#include <cuda_runtime.h>
#include <cuda_fp16.h>
#include <cstdint>

#define BATCH 32768
#define IN1   784
#define KPAD  832          // 13 * 64 (zero-padded)
#define HID   256
#define OUT   10
#define W1B   98
#define W2B   32
#define KC    64
#define NCHUNK 13
#define BM    64
#define NTHR  288          // 8 consumer warps + 1 producer warp

// -------- device scratch (allocation-free rule) --------
__device__ __align__(16) __half g_w1h[HID * KPAD];   // [256][832] fp16 {-1,0,+1}
__device__ float g_w2f[OUT * HID];                   // [10][256] fp32 (incl alpha2)

// -------- shared memory layout (bytes) --------
#define SM_X(s)   ((s) * 16384)            // x fp32 ring: 64 x 64 fp32 = 16KB x2
#define SM_A16(s) (32768 + (s) * 8192)     // A fp16: 64 x 64 = 8KB x2
#define SM_B(s)   (49152 + (s) * 32768)    // B fp16: 256 x 64 = 32KB x2
#define SM_BAR    114688                   // full[2] @ +0,+8 ; empty[2] @ +16,+24
#define SM_W2     0                        // epilogue alias
#define SM_PART   16384                    // epilogue alias
#define SMEM_TOTAL 114752                  // x2 = 229.4KB <= 233KB/SM -> occ 2

// -------- helpers --------
__device__ __forceinline__ uint32_t smem_u32(const void* p) {
    uint32_t a;
    asm("{ .reg .u64 t; cvta.to.shared.u64 t, %1; cvt.u32.u64 %0, t; }" : "=r"(a) : "l"(p));
    return a;
}
__device__ __forceinline__ uint32_t swz(uint32_t off) {  // SW128
    return off ^ ((off >> 3) & 0x70);
}
__device__ __forceinline__ uint32_t cvt2h(float lo, float hi) {  // -> {lo | hi<<16}
    uint32_t r;
    asm("cvt.rn.f16x2.f32 %0, %1, %2;" : "=r"(r) : "f"(hi), "f"(lo));
    return r;
}
__device__ __forceinline__ void ldm_x4(uint32_t& r0, uint32_t& r1, uint32_t& r2, uint32_t& r3,
                                       uint32_t addr) {
    asm volatile("ldmatrix.sync.aligned.m8n8.x4.shared.b16 {%0,%1,%2,%3}, [%4];"
                 : "=r"(r0), "=r"(r1), "=r"(r2), "=r"(r3) : "r"(addr));
}
__device__ __forceinline__ void mma16816(float* d, const uint32_t* a, const uint32_t* b) {
    asm volatile(
        "mma.sync.aligned.m16n8k16.row.col.f32.f16.f16.f32 "
        "{%0,%1,%2,%3}, {%4,%5,%6,%7}, {%8,%9}, {%0,%1,%2,%3};"
        : "+f"(d[0]), "+f"(d[1]), "+f"(d[2]), "+f"(d[3])
        : "r"(a[0]), "r"(a[1]), "r"(a[2]), "r"(a[3]), "r"(b[0]), "r"(b[1]));
}
__device__ __forceinline__ void cpa16(uint32_t dst, const void* src) {
    asm volatile("cp.async.cg.shared.global [%0], [%1], 16;" :: "r"(dst), "l"(src) : "memory");
}
__device__ __forceinline__ void cpcommit() {
    asm volatile("cp.async.commit_group;" ::: "memory");
}
__device__ __forceinline__ void mbar_init(uint32_t mbar, uint32_t cnt) {
    asm volatile("mbarrier.init.shared.b64 [%0], %1;" :: "r"(mbar), "r"(cnt) : "memory");
}
__device__ __forceinline__ void mbar_arrive(uint32_t mbar) {
    asm volatile("mbarrier.arrive.shared.b64 _, [%0];" :: "r"(mbar) : "memory");
}
__device__ __forceinline__ void cpasync_arrive_noinc(uint32_t mbar) {
    asm volatile("cp.async.mbarrier.arrive.noinc.shared.b64 [%0];" :: "r"(mbar) : "memory");
}
__device__ __forceinline__ void mbar_wait(uint32_t mbar, uint32_t parity) {
    asm volatile(
        "{\n\t.reg .pred P;\n"
        "WL_%=:\n\t"
        "mbarrier.try_wait.parity.acquire.cta.shared::cta.b64 P, [%0], %1, 0x989680;\n\t"
        "@P bra.uni WD_%=;\n\t"
        "bra.uni WL_%=;\n"
        "WD_%=:\n\t}"
        :: "r"(mbar), "r"(parity) : "memory");
}

// ---------------------------------------------------------------------------
__global__ void unpack_all(const int* __restrict__ w1p, const int* __restrict__ m1p,
                           const int* __restrict__ w2p, const int* __restrict__ m2p,
                           const float* __restrict__ a2) {
    int idx = blockIdx.x * 256 + threadIdx.x;
    if (idx < HID * KPAD) {
        int o = idx / KPAD, i = idx - o * KPAD;
        float v = 0.0f;
        if (i < IN1) {
            int sh = 7 - (i & 7);
            int wb = (w1p[o * W1B + (i >> 3)] >> sh) & 1;
            int mb = (m1p[o * W1B + (i >> 3)] >> sh) & 1;
            v = (2.0f * (float)wb - 1.0f) * (float)mb;
        }
        g_w1h[idx] = __float2half_rn(v);
    } else {
        int j = idx - HID * KPAD;
        if (j < OUT * HID) {
            int o = j / HID, i = j - o * HID;
            int sh = 7 - (i & 7);
            int wb = (w2p[o * W2B + (i >> 3)] >> sh) & 1;
            int mb = (m2p[o * W2B + (i >> 3)] >> sh) & 1;
            g_w2f[j] = (2.0f * (float)wb - 1.0f) * (float)mb * a2[0];
        }
    }
}

// ---------------------------------------------------------------------------
// Warp-specialized, 2 CTAs/SM.
//   warps 0-7 (256 thr): consumers — wait full -> LDSM+MMA -> arrive empty.
//   warp  8   (32 thr):  producer — B cp.async, X cp.async, fp32->fp16 convert.
// full[s]: 64 = 32 cp.async-noinc (B) + 32 arrives (post A16 STS).
// empty[s]: 256 consumer arrives. 2 stages.
// ---------------------------------------------------------------------------
__global__ void __launch_bounds__(NTHR, 2)
fused(const float* __restrict__ x, const float* __restrict__ alpha1,
      float* __restrict__ out) {
    extern __shared__ char smem[];
    const uint32_t sb = smem_u32(smem);
    const int tid = threadIdx.x, wid = tid >> 5, lane = tid & 31;
    const int bm = blockIdx.x * BM;
    const float* __restrict__ xb = x + (size_t)bm * IN1;

    if (tid == 0) {
        mbar_init(sb + SM_BAR + 0, 64);    // full[0]
        mbar_init(sb + SM_BAR + 8, 64);    // full[1]
        mbar_init(sb + SM_BAR + 16, 256);  // empty[0]
        mbar_init(sb + SM_BAR + 24, 256);  // empty[1]
    }
    __syncthreads();

    float acc[2][8][4];
    #pragma unroll
    for (int i = 0; i < 2; ++i)
        #pragma unroll
        for (int j = 0; j < 8; ++j)
            #pragma unroll
            for (int r = 0; r < 4; ++r) acc[i][j][r] = 0.0f;

    if (wid == 8) {
        // ===================== PRODUCER (32 threads) =====================
        const int pt = lane;
        // prologue: X(0) in flight (group 0)
        {
            #pragma unroll
            for (int it = 0; it < 32; ++it) {
                int idx = pt + it * 32;
                int row = idx >> 4, f = idx & 15;
                cpa16(sb + SM_X(0) + (uint32_t)(row * 256 + f * 16),
                      xb + (size_t)row * IN1 + f * 4);
            }
            cpcommit();
        }
        #pragma unroll 1
        for (int c = 0; c < NCHUNK; ++c) {
            const int st = c & 1;
            const uint32_t fullb  = sb + SM_BAR + st * 8;
            const uint32_t emptyb = sb + SM_BAR + 16 + st * 8;
            mbar_wait(emptyb, 1u ^ (uint32_t)((c >> 1) & 1));
            // ---- B(c): cp.async, 64 (tail:16) granules/thread ----
            if (c == NCHUNK - 1) {
                #pragma unroll
                for (int it = 0; it < 16; ++it) {
                    int idx = pt + it * 32;
                    int n = idx >> 1, u = idx & 1;
                    cpa16(sb + SM_B(st) + swz((uint32_t)(n * 128 + u * 16)),
                          g_w1h + (size_t)n * KPAD + 768 + u * 8);
                }
            } else {
                const int kt = c * KC;
                #pragma unroll
                for (int it = 0; it < 64; ++it) {
                    int idx = pt + it * 32;
                    int n = idx >> 3, u = idx & 7;
                    cpa16(sb + SM_B(st) + swz((uint32_t)(n * 128 + u * 16)),
                          g_w1h + (size_t)n * KPAD + kt + u * 8);
                }
            }
            cpcommit();
            cpasync_arrive_noinc(fullb);           // B counts on full when done
            // ---- X(c+1) prefetch ----
            if (c + 1 < NCHUNK) {
                const int s1 = (c + 1) & 1;
                if (c + 1 == NCHUNK - 1) {
                    #pragma unroll
                    for (int it = 0; it < 8; ++it) {
                        int idx = pt + it * 32;            // 0..255
                        int row = idx >> 2, f = idx & 3;
                        cpa16(sb + SM_X(s1) + (uint32_t)(row * 256 + f * 16),
                              xb + (size_t)row * IN1 + 768 + f * 4);
                    }
                } else {
                    const int kt1 = (c + 1) * KC;
                    #pragma unroll
                    for (int it = 0; it < 32; ++it) {
                        int idx = pt + it * 32;
                        int row = idx >> 4, f = idx & 15;
                        cpa16(sb + SM_X(s1) + (uint32_t)(row * 256 + f * 16),
                              xb + (size_t)row * IN1 + kt1 + f * 4);
                    }
                }
                cpcommit();
                asm volatile("cp.async.wait_group 1;" ::: "memory");  // X(c) done
            } else {
                asm volatile("cp.async.wait_group 0;" ::: "memory");
            }
            // ---- convert X(c) -> A16[st] (self-issued granules only) ----
            if (c == NCHUNK - 1) {
                #pragma unroll
                for (int it = 0; it < 8; ++it) {
                    int idx = pt + it * 32;
                    int row = idx >> 2, f = idx & 3;
                    float4 v = *reinterpret_cast<const float4*>(
                        smem + SM_X(st) + row * 256 + f * 16);
                    *reinterpret_cast<uint2*>(smem + SM_A16(st) +
                        swz((uint32_t)(row * 128 + f * 8))) =
                        make_uint2(cvt2h(v.x, v.y), cvt2h(v.z, v.w));
                }
            } else {
                #pragma unroll
                for (int it = 0; it < 32; ++it) {
                    int idx = pt + it * 32;
                    int row = idx >> 4, f = idx & 15;
                    float4 v = *reinterpret_cast<const float4*>(
                        smem + SM_X(st) + row * 256 + f * 16);
                    *reinterpret_cast<uint2*>(smem + SM_A16(st) +
                        swz((uint32_t)(row * 128 + f * 8))) =
                        make_uint2(cvt2h(v.x, v.y), cvt2h(v.z, v.w));
                }
            }
            mbar_arrive(fullb);                    // A16 visible (release)
        }
    } else {
        // ===================== CONSUMERS (256 threads) =====================
        const int wm = wid >> 2, wn = wid & 3;    // 2x4 grid, 32x64 warp tiles
        const int g = lane >> 3, lr = lane & 7;
        #pragma unroll 1
        for (int c = 0; c < NCHUNK; ++c) {
            const int st = c & 1;
            const uint32_t fullb  = sb + SM_BAR + st * 8;
            const uint32_t emptyb = sb + SM_BAR + 16 + st * 8;
            mbar_wait(fullb, (uint32_t)((c >> 1) & 1));
            const int nks = (c == NCHUNK - 1) ? 1 : 4;
            #pragma unroll
            for (int ks = 0; ks < 4; ++ks) {
                if (ks >= nks) break;
                uint32_t b[8][2];
                #pragma unroll
                for (int p = 0; p < 4; ++p) {
                    int n  = wn * 64 + p * 16 + ((g & 2) ? 8 : 0) + lr;
                    int kk = ks * 16 + ((g & 1) ? 8 : 0);
                    ldm_x4(b[2 * p][0], b[2 * p][1], b[2 * p + 1][0], b[2 * p + 1][1],
                           sb + SM_B(st) + swz((uint32_t)(n * 128 + kk * 2)));
                }
                uint32_t a[2][4];
                #pragma unroll
                for (int i = 0; i < 2; ++i) {
                    int row = wm * 32 + i * 16 + ((g & 1) ? 8 : 0) + lr;
                    int kk  = ks * 16 + ((g & 2) ? 8 : 0);
                    ldm_x4(a[i][0], a[i][1], a[i][2], a[i][3],
                           sb + SM_A16(st) + swz((uint32_t)(row * 128 + kk * 2)));
                }
                #pragma unroll
                for (int i = 0; i < 2; ++i)
                    #pragma unroll
                    for (int j = 0; j < 8; ++j) mma16816(acc[i][j], a[i], b[j]);
            }
            mbar_arrive(emptyb);
        }
    }

    // ---- epilogue: out = relu(a1*acc) @ w2^T ----
    const float a1v = alpha1[0];
    __syncthreads();                               // join producer+consumers
    for (int i = tid; i < OUT * HID; i += NTHR)
        reinterpret_cast<float*>(smem + SM_W2)[i] = g_w2f[i];
    __syncthreads();

    if (wid < 8) {
        const int wm = wid >> 2, wn = wid & 3;
        #pragma unroll
        for (int i = 0; i < 2; ++i)
            #pragma unroll
            for (int j = 0; j < 8; ++j)
                #pragma unroll
                for (int r = 0; r < 4; ++r)
                    acc[i][j][r] = fmaxf(a1v * acc[i][j][r], 0.0f);

        const float* w2s = reinterpret_cast<const float*>(smem + SM_W2);
        float* part = reinterpret_cast<float*>(smem + SM_PART);
        const int q = lane & 3, gq = lane >> 2;
        #pragma unroll
        for (int o = 0; o < OUT; ++o) {
            float w2v[8][2];
            #pragma unroll
            for (int j = 0; j < 8; ++j) {
                w2v[j][0] = w2s[o * HID + wn * 64 + j * 8 + q * 2];
                w2v[j][1] = w2s[o * HID + wn * 64 + j * 8 + q * 2 + 1];
            }
            #pragma unroll
            for (int i = 0; i < 2; ++i)
                #pragma unroll
                for (int h2 = 0; h2 < 2; ++h2) {
                    float s = 0.0f;
                    #pragma unroll
                    for (int j = 0; j < 8; ++j)
                        s += acc[i][j][h2 * 2] * w2v[j][0] + acc[i][j][h2 * 2 + 1] * w2v[j][1];
                    s += __shfl_xor_sync(0xffffffffu, s, 1);
                    s += __shfl_xor_sync(0xffffffffu, s, 2);
                    if (q == 0) {
                        int row = wm * 32 + i * 16 + h2 * 8 + gq;
                        part[wn * (BM * OUT) + row * OUT + o] = s;
                    }
                }
        }
    }
    __syncthreads();

    {
        const float* part = reinterpret_cast<const float*>(smem + SM_PART);
        for (int idx = tid; idx < BM * OUT; idx += NTHR) {
            float v = part[idx] + part[BM * OUT + idx] +
                      part[2 * BM * OUT + idx] + part[3 * BM * OUT + idx];
            out[(size_t)bm * OUT + idx] = v;
        }
    }
}

// ---------------------------------------------------------------------------
extern "C" void kernel_launch(void* const* d_in, const int* in_sizes, int n_in,
                              void* d_out, int out_size) {
    const float* x   = (const float*)d_in[0];
    const int*   w1p = (const int*)d_in[1];
    const int*   m1p = (const int*)d_in[2];
    const float* a1  = (const float*)d_in[3];
    const int*   w2p = (const int*)d_in[4];
    const int*   m2p = (const int*)d_in[5];
    const float* a2  = (const float*)d_in[6];
    float* out = (float*)d_out;

    cudaFuncSetAttribute(fused, cudaFuncAttributeMaxDynamicSharedMemorySize, SMEM_TOTAL);

    int total = HID * KPAD + OUT * HID;
    unpack_all<<<(total + 255) / 256, 256>>>(w1p, m1p, w2p, m2p, a2);
    fused<<<BATCH / BM, NTHR, SMEM_TOTAL>>>(x, a1, out);
}

// round 14
// speedup vs baseline: 1.8478x; 1.8478x over previous
#include <cuda_runtime.h>
#include <cuda_fp16.h>
#include <cstdint>

#define BATCH 32768
#define IN1   784
#define KPAD  832          // 13 * 64 (zero-padded)
#define HID   256
#define OUT   10
#define W1B   98
#define W2B   32
#define KC    64
#define NCHUNK 13
#define BM    64
#define NTHR  256

// -------- device scratch (allocation-free rule) --------
__device__ __align__(16) __half g_w1h[HID * KPAD];   // [256][832] fp16 {-1,0,+1}
__device__ float g_w2f[OUT * HID];                   // [10][256] fp32 (incl alpha2)

// -------- shared memory layout (bytes) --------
#define SM_X(s)   ((s) * 16384)            // x fp32 ring: 64 x 64 fp32 = 16KB x2
#define SM_A16(s) (32768 + (s) * 8192)     // A fp16: 64 x 64 = 8KB x2
#define SM_B(s)   (49152 + (s) * 32768)    // B fp16: 256 x 64 = 32KB x2
#define SM_W2     0                        // epilogue alias
#define SM_PART   16384                    // epilogue alias
#define SMEM_TOTAL 114688                  // 112KB -> 2 CTAs/SM

// -------- helpers --------
__device__ __forceinline__ uint32_t smem_u32(const void* p) {
    uint32_t a;
    asm("{ .reg .u64 t; cvta.to.shared.u64 t, %1; cvt.u32.u64 %0, t; }" : "=r"(a) : "l"(p));
    return a;
}
__device__ __forceinline__ uint32_t swz(uint32_t off) {  // SW128
    return off ^ ((off >> 3) & 0x70);
}
__device__ __forceinline__ uint32_t cvt2h(float lo, float hi) {  // -> {lo | hi<<16}
    uint32_t r;
    asm("cvt.rn.f16x2.f32 %0, %1, %2;" : "=r"(r) : "f"(hi), "f"(lo));
    return r;
}
__device__ __forceinline__ void ldm_x4(uint32_t& r0, uint32_t& r1, uint32_t& r2, uint32_t& r3,
                                       uint32_t addr) {
    asm volatile("ldmatrix.sync.aligned.m8n8.x4.shared.b16 {%0,%1,%2,%3}, [%4];"
                 : "=r"(r0), "=r"(r1), "=r"(r2), "=r"(r3) : "r"(addr));
}
__device__ __forceinline__ void mma16816(float* d, const uint32_t* a, const uint32_t* b) {
    asm volatile(
        "mma.sync.aligned.m16n8k16.row.col.f32.f16.f16.f32 "
        "{%0,%1,%2,%3}, {%4,%5,%6,%7}, {%8,%9}, {%0,%1,%2,%3};"
        : "+f"(d[0]), "+f"(d[1]), "+f"(d[2]), "+f"(d[3])
        : "r"(a[0]), "r"(a[1]), "r"(a[2]), "r"(a[3]), "r"(b[0]), "r"(b[1]));
}
__device__ __forceinline__ void cpa16(uint32_t dst, const void* src) {
    asm volatile("cp.async.cg.shared.global [%0], [%1], 16;" :: "r"(dst), "l"(src) : "memory");
}
__device__ __forceinline__ void cpcommit() {
    asm volatile("cp.async.commit_group;" ::: "memory");
}

// ---------------------------------------------------------------------------
__global__ void unpack_all(const int* __restrict__ w1p, const int* __restrict__ m1p,
                           const int* __restrict__ w2p, const int* __restrict__ m2p,
                           const float* __restrict__ a2) {
    int idx = blockIdx.x * 256 + threadIdx.x;
    if (idx < HID * KPAD) {
        int o = idx / KPAD, i = idx - o * KPAD;
        float v = 0.0f;
        if (i < IN1) {
            int sh = 7 - (i & 7);
            int wb = (w1p[o * W1B + (i >> 3)] >> sh) & 1;
            int mb = (m1p[o * W1B + (i >> 3)] >> sh) & 1;
            v = (2.0f * (float)wb - 1.0f) * (float)mb;
        }
        g_w1h[idx] = __float2half_rn(v);
    } else {
        int j = idx - HID * KPAD;
        if (j < OUT * HID) {
            int o = j / HID, i = j - o * HID;
            int sh = 7 - (i & 7);
            int wb = (w2p[o * W2B + (i >> 3)] >> sh) & 1;
            int mb = (m2p[o * W2B + (i >> 3)] >> sh) & 1;
            g_w2f[j] = (2.0f * (float)wb - 1.0f) * (float)mb * a2[0];
        }
    }
}

// ---------------------------------------------------------------------------
// Fused, 2 CTAs/SM. x flows GMEM --cp.async--> fp32 smem ring --LDS/cvt/STS-->
// fp16 A tiles. B via cp.async. D[64,256] fp16 mma w/ fp32 acc; fused layer 2.
// Round-9 structure; convert of chunk c+1 interleaved into compute of chunk c.
// ---------------------------------------------------------------------------
__global__ void __launch_bounds__(NTHR, 2)
fused(const float* __restrict__ x, const float* __restrict__ alpha1,
      float* __restrict__ out) {
    extern __shared__ char smem[];
    const uint32_t sb = smem_u32(smem);
    const int tid = threadIdx.x, wid = tid >> 5, lane = tid & 31;
    const int wm = wid >> 2, wn = wid & 3;        // 2x4 warp grid, 32x64 warp tiles
    const int bm = blockIdx.x * BM;
    const float* __restrict__ xb = x + (size_t)bm * IN1;

    float acc[2][8][4];
    #pragma unroll
    for (int i = 0; i < 2; ++i)
        #pragma unroll
        for (int j = 0; j < 8; ++j)
            #pragma unroll
            for (int r = 0; r < 4; ++r) acc[i][j][r] = 0.0f;

    const int g = lane >> 3, lr = lane & 7;

    // ---- async issue helpers ----
    auto issueX = [&](int c, int s) {              // 1024 granules, 4/thread
        const int kt = c * KC;
        #pragma unroll
        for (int it = 0; it < 4; ++it) {
            int idx = tid + it * NTHR;
            int row = idx >> 4, f = idx & 15;
            cpa16(sb + SM_X(s) + (uint32_t)(row * 256 + f * 16),
                  xb + (size_t)row * IN1 + kt + f * 4);
        }
        cpcommit();
    };
    auto issueX_tail = [&](int s) {                // chunk 12: cols 768..783 (f<4)
        int row = tid >> 2, f = tid & 3;
        cpa16(sb + SM_X(s) + (uint32_t)(row * 256 + f * 16),
              xb + (size_t)row * IN1 + 768 + f * 4);
        cpcommit();
    };
    auto issueB = [&](int c, int s) {              // 2048 granules, 8/thread
        const int kt = c * KC;
        #pragma unroll
        for (int it = 0; it < 8; ++it) {
            int idx = tid + it * NTHR;
            int n = idx >> 3, u = idx & 7;
            cpa16(sb + SM_B(s) + swz((uint32_t)(n * 128 + u * 16)),
                  g_w1h + (size_t)n * KPAD + kt + u * 8);
        }
        cpcommit();
    };
    auto issueB_tail = [&](int s) {                // only u<2 (valid 16 cols)
        #pragma unroll
        for (int it = 0; it < 2; ++it) {
            int idx = tid + it * NTHR;
            int n = idx >> 1, u = idx & 1;
            cpa16(sb + SM_B(s) + swz((uint32_t)(n * 128 + u * 16)),
                  g_w1h + (size_t)n * KPAD + 768 + u * 8);
        }
        cpcommit();
    };
    // ---- fp32 smem -> fp16 smem conversion ----
    auto convPiece = [&](int s, int it) {          // one of 4 iterations
        int idx = tid + it * NTHR;
        int row = idx >> 4, f = idx & 15;
        float4 v = *reinterpret_cast<const float4*>(smem + SM_X(s) + row * 256 + f * 16);
        uint32_t sw = swz((uint32_t)(row * 128 + f * 8));
        *reinterpret_cast<uint2*>(smem + SM_A16(s) + sw) =
            make_uint2(cvt2h(v.x, v.y), cvt2h(v.z, v.w));
    };
    auto convertA = [&](int s) {
        #pragma unroll
        for (int it = 0; it < 4; ++it) convPiece(s, it);
    };
    auto convertA_tail = [&](int s) {              // 16 valid cols only
        int row = tid >> 2, f = tid & 3;
        float4 v = *reinterpret_cast<const float4*>(smem + SM_X(s) + row * 256 + f * 16);
        uint32_t sw = swz((uint32_t)(row * 128 + f * 8));
        *reinterpret_cast<uint2*>(smem + SM_A16(s) + sw) =
            make_uint2(cvt2h(v.x, v.y), cvt2h(v.z, v.w));
    };
    auto computeKS = [&](int st, int sa2, int ks) {
        uint32_t b[8][2];
        #pragma unroll
        for (int p = 0; p < 4; ++p) {
            int n  = wn * 64 + p * 16 + ((g & 2) ? 8 : 0) + lr;
            int kk = ks * 16 + ((g & 1) ? 8 : 0);
            ldm_x4(b[2 * p][0], b[2 * p][1], b[2 * p + 1][0], b[2 * p + 1][1],
                   sb + SM_B(st) + swz((uint32_t)(n * 128 + kk * 2)));
        }
        uint32_t a[2][4];
        #pragma unroll
        for (int i = 0; i < 2; ++i) {
            int row = wm * 32 + i * 16 + ((g & 1) ? 8 : 0) + lr;
            int kk  = ks * 16 + ((g & 2) ? 8 : 0);
            ldm_x4(a[i][0], a[i][1], a[i][2], a[i][3],
                   sb + SM_A16(sa2) + swz((uint32_t)(row * 128 + kk * 2)));
        }
        #pragma unroll
        for (int i = 0; i < 2; ++i)
            #pragma unroll
            for (int j = 0; j < 8; ++j) mma16816(acc[i][j], a[i], b[j]);
    };

    // ---- prologue: groups X0 | B0 | X1 ----
    issueX(0, 0);
    issueB(0, 0);
    issueX(1, 1);
    asm volatile("cp.async.wait_group 2;" ::: "memory");   // X0 done
    convertA(0);
    asm volatile("cp.async.wait_group 1;" ::: "memory");   // B0 done (X1 pending)
    __syncthreads();

    // ---- mainloop: iter c consumes A16[c&1], B[c&1]; entry pending {X(c+1)} ----
    for (int c = 0; c < NCHUNK; ++c) {
        if (c + 1 < NCHUNK) {
            if (c + 1 == NCHUNK - 1) issueB_tail((c + 1) & 1);
            else                     issueB(c + 1, (c + 1) & 1);
        }
        if (c + 2 < NCHUNK) {
            if (c + 2 == NCHUNK - 1) issueX_tail((c + 2) & 1);
            else                     issueX(c + 2, (c + 2) & 1);
        }
        // early wait: X(c+1) ready before interleaved convert (issued 1 chunk ago)
        if (c + 1 < NCHUNK) {
            if (c + 2 < NCHUNK)
                asm volatile("cp.async.wait_group 2;" ::: "memory");
            else
                asm volatile("cp.async.wait_group 1;" ::: "memory");
        }
        if (c == NCHUNK - 1) {
            computeKS(c & 1, c & 1, 0);            // trimmed tail: K=16, no conv
        } else if (c == NCHUNK - 2) {
            computeKS(c & 1, c & 1, 0);
            convertA_tail((c + 1) & 1);            // next chunk has 1 conv piece
            computeKS(c & 1, c & 1, 1);
            computeKS(c & 1, c & 1, 2);
            computeKS(c & 1, c & 1, 3);
        } else {
            #pragma unroll
            for (int ks = 0; ks < 4; ++ks) {
                computeKS(c & 1, c & 1, ks);
                convPiece((c + 1) & 1, ks);        // hide convert under MMA stream
            }
        }
        if (c + 1 < NCHUNK) {
            if (c + 2 < NCHUNK)
                asm volatile("cp.async.wait_group 1;" ::: "memory");  // B(c+1) done
            else
                asm volatile("cp.async.wait_group 0;" ::: "memory");
            __syncthreads();
        }
    }

    // ---- epilogue: out = relu(a1*acc) @ w2^T ----
    const float a1v = alpha1[0];
    #pragma unroll
    for (int i = 0; i < 2; ++i)
        #pragma unroll
        for (int j = 0; j < 8; ++j)
            #pragma unroll
            for (int r = 0; r < 4; ++r)
                acc[i][j][r] = fmaxf(a1v * acc[i][j][r], 0.0f);

    __syncthreads();                               // mainloop smem dead; alias
    for (int i = tid; i < OUT * HID; i += NTHR)
        reinterpret_cast<float*>(smem + SM_W2)[i] = g_w2f[i];
    __syncthreads();

    const float* w2s = reinterpret_cast<const float*>(smem + SM_W2);
    float* part = reinterpret_cast<float*>(smem + SM_PART);
    const int q = lane & 3, gq = lane >> 2;

    #pragma unroll
    for (int o = 0; o < OUT; ++o) {
        float w2v[8][2];
        #pragma unroll
        for (int j = 0; j < 8; ++j) {
            w2v[j][0] = w2s[o * HID + wn * 64 + j * 8 + q * 2];
            w2v[j][1] = w2s[o * HID + wn * 64 + j * 8 + q * 2 + 1];
        }
        #pragma unroll
        for (int i = 0; i < 2; ++i)
            #pragma unroll
            for (int h2 = 0; h2 < 2; ++h2) {
                float s = 0.0f;
                #pragma unroll
                for (int j = 0; j < 8; ++j)
                    s += acc[i][j][h2 * 2] * w2v[j][0] + acc[i][j][h2 * 2 + 1] * w2v[j][1];
                s += __shfl_xor_sync(0xffffffffu, s, 1);
                s += __shfl_xor_sync(0xffffffffu, s, 2);
                if (q == 0) {
                    int row = wm * 32 + i * 16 + h2 * 8 + gq;
                    part[wn * (BM * OUT) + row * OUT + o] = s;
                }
            }
    }
    __syncthreads();

    for (int idx = tid; idx < BM * OUT; idx += NTHR) {
        float v = part[idx] + part[BM * OUT + idx] +
                  part[2 * BM * OUT + idx] + part[3 * BM * OUT + idx];
        out[(size_t)bm * OUT + idx] = v;
    }
}

// ---------------------------------------------------------------------------
extern "C" void kernel_launch(void* const* d_in, const int* in_sizes, int n_in,
                              void* d_out, int out_size) {
    const float* x   = (const float*)d_in[0];
    const int*   w1p = (const int*)d_in[1];
    const int*   m1p = (const int*)d_in[2];
    const float* a1  = (const float*)d_in[3];
    const int*   w2p = (const int*)d_in[4];
    const int*   m2p = (const int*)d_in[5];
    const float* a2  = (const float*)d_in[6];
    float* out = (float*)d_out;

    cudaFuncSetAttribute(fused, cudaFuncAttributeMaxDynamicSharedMemorySize, SMEM_TOTAL);

    int total = HID * KPAD + OUT * HID;
    unpack_all<<<(total + 255) / 256, 256>>>(w1p, m1p, w2p, m2p, a2);
    fused<<<BATCH / BM, NTHR, SMEM_TOTAL>>>(x, a1, out);
}

// round 15
// speedup vs baseline: 1.9214x; 1.0398x over previous
#include <cuda_runtime.h>
#include <cuda_fp16.h>
#include <cstdint>

#define BATCH 32768
#define IN1   784
#define KPAD  832          // 13 * 64 (zero-padded)
#define HID   256
#define OUT   10
#define W1B   98
#define W2B   32
#define KC    64
#define NCHUNK 13
#define BM    64
#define NTHR  256

// -------- device scratch (allocation-free rule) --------
__device__ __align__(16) __half g_w1h[HID * KPAD];   // [256][832] fp16 {-1,0,+1}
__device__ float g_w2f[OUT * HID];                   // [10][256] fp32 (incl alpha2)

// -------- shared memory layout (bytes) --------
#define SM_X(s)   ((s) * 16384)            // x fp32 ring: 64 x 64 fp32 = 16KB x2
#define SM_A16(s) (32768 + (s) * 8192)     // A fp16: 64 x 64 = 8KB x2
#define SM_B(s)   (49152 + (s) * 32768)    // B fp16: 256 x 64 = 32KB x2
#define SM_W2     0                        // epilogue alias
#define SM_PART   16384                    // epilogue alias
#define SMEM_TOTAL 114688                  // 112KB -> 2 CTAs/SM

// -------- helpers --------
__device__ __forceinline__ uint32_t smem_u32(const void* p) {
    uint32_t a;
    asm("{ .reg .u64 t; cvta.to.shared.u64 t, %1; cvt.u32.u64 %0, t; }" : "=r"(a) : "l"(p));
    return a;
}
__device__ __forceinline__ uint32_t swz(uint32_t off) {  // SW128
    return off ^ ((off >> 3) & 0x70);
}
__device__ __forceinline__ uint32_t cvt2h(float lo, float hi) {  // -> {lo | hi<<16}
    uint32_t r;
    asm("cvt.rn.f16x2.f32 %0, %1, %2;" : "=r"(r) : "f"(hi), "f"(lo));
    return r;
}
__device__ __forceinline__ void ldm_x4(uint32_t& r0, uint32_t& r1, uint32_t& r2, uint32_t& r3,
                                       uint32_t addr) {
    asm volatile("ldmatrix.sync.aligned.m8n8.x4.shared.b16 {%0,%1,%2,%3}, [%4];"
                 : "=r"(r0), "=r"(r1), "=r"(r2), "=r"(r3) : "r"(addr));
}
__device__ __forceinline__ void mma16816(float* d, const uint32_t* a, const uint32_t* b) {
    asm volatile(
        "mma.sync.aligned.m16n8k16.row.col.f32.f16.f16.f32 "
        "{%0,%1,%2,%3}, {%4,%5,%6,%7}, {%8,%9}, {%0,%1,%2,%3};"
        : "+f"(d[0]), "+f"(d[1]), "+f"(d[2]), "+f"(d[3])
        : "r"(a[0]), "r"(a[1]), "r"(a[2]), "r"(a[3]), "r"(b[0]), "r"(b[1]));
}
__device__ __forceinline__ void cpa16(uint32_t dst, const void* src) {
    asm volatile("cp.async.cg.shared.global [%0], [%1], 16;" :: "r"(dst), "l"(src) : "memory");
}
__device__ __forceinline__ void cpcommit() {
    asm volatile("cp.async.commit_group;" ::: "memory");
}

// ---------------------------------------------------------------------------
__global__ void unpack_all(const int* __restrict__ w1p, const int* __restrict__ m1p,
                           const int* __restrict__ w2p, const int* __restrict__ m2p,
                           const float* __restrict__ a2) {
    int idx = blockIdx.x * 256 + threadIdx.x;
    if (idx < HID * KPAD) {
        int o = idx / KPAD, i = idx - o * KPAD;
        float v = 0.0f;
        if (i < IN1) {
            int sh = 7 - (i & 7);
            int wb = (w1p[o * W1B + (i >> 3)] >> sh) & 1;
            int mb = (m1p[o * W1B + (i >> 3)] >> sh) & 1;
            v = (2.0f * (float)wb - 1.0f) * (float)mb;
        }
        g_w1h[idx] = __float2half_rn(v);
    } else {
        int j = idx - HID * KPAD;
        if (j < OUT * HID) {
            int o = j / HID, i = j - o * HID;
            int sh = 7 - (i & 7);
            int wb = (w2p[o * W2B + (i >> 3)] >> sh) & 1;
            int mb = (m2p[o * W2B + (i >> 3)] >> sh) & 1;
            g_w2f[j] = (2.0f * (float)wb - 1.0f) * (float)mb * a2[0];
        }
    }
}

// ---------------------------------------------------------------------------
// Fused, 2 CTAs/SM. x flows GMEM --cp.async--> fp32 smem ring --LDS/cvt/STS-->
// fp16 A tiles. B via cp.async. D[64,256] fp16 mma w/ fp32 acc; fused layer 2.
// Round-9 structure; ks order staggered by warp row (wm) to de-correlate the
// LDSM and MMA phases across the resident warps.
// ---------------------------------------------------------------------------
__global__ void __launch_bounds__(NTHR, 2)
fused(const float* __restrict__ x, const float* __restrict__ alpha1,
      float* __restrict__ out) {
    extern __shared__ char smem[];
    const uint32_t sb = smem_u32(smem);
    const int tid = threadIdx.x, wid = tid >> 5, lane = tid & 31;
    const int wm = wid >> 2, wn = wid & 3;        // 2x4 warp grid, 32x64 warp tiles
    const int bm = blockIdx.x * BM;
    const float* __restrict__ xb = x + (size_t)bm * IN1;

    float acc[2][8][4];
    #pragma unroll
    for (int i = 0; i < 2; ++i)
        #pragma unroll
        for (int j = 0; j < 8; ++j)
            #pragma unroll
            for (int r = 0; r < 4; ++r) acc[i][j][r] = 0.0f;

    const int g = lane >> 3, lr = lane & 7;
    const int ks0 = wm << 1;                       // stagger: wm=0 -> 0, wm=1 -> 2

    // ---- async issue helpers ----
    auto issueX = [&](int c, int s) {              // 1024 granules, 4/thread
        const int kt = c * KC;
        #pragma unroll
        for (int it = 0; it < 4; ++it) {
            int idx = tid + it * NTHR;
            int row = idx >> 4, f = idx & 15;
            cpa16(sb + SM_X(s) + (uint32_t)(row * 256 + f * 16),
                  xb + (size_t)row * IN1 + kt + f * 4);
        }
        cpcommit();
    };
    auto issueX_tail = [&](int s) {                // chunk 12: cols 768..783 (f<4)
        int row = tid >> 2, f = tid & 3;
        cpa16(sb + SM_X(s) + (uint32_t)(row * 256 + f * 16),
              xb + (size_t)row * IN1 + 768 + f * 4);
        cpcommit();
    };
    auto issueB = [&](int c, int s) {              // 2048 granules, 8/thread
        const int kt = c * KC;
        #pragma unroll
        for (int it = 0; it < 8; ++it) {
            int idx = tid + it * NTHR;
            int n = idx >> 3, u = idx & 7;
            cpa16(sb + SM_B(s) + swz((uint32_t)(n * 128 + u * 16)),
                  g_w1h + (size_t)n * KPAD + kt + u * 8);
        }
        cpcommit();
    };
    auto issueB_tail = [&](int s) {                // only u<2 (valid 16 cols)
        #pragma unroll
        for (int it = 0; it < 2; ++it) {
            int idx = tid + it * NTHR;
            int n = idx >> 1, u = idx & 1;
            cpa16(sb + SM_B(s) + swz((uint32_t)(n * 128 + u * 16)),
                  g_w1h + (size_t)n * KPAD + 768 + u * 8);
        }
        cpcommit();
    };
    // ---- fp32 smem -> fp16 smem conversion (round-9 verbatim) ----
    auto convertA = [&](int s) {
        #pragma unroll
        for (int it = 0; it < 4; ++it) {
            int idx = tid + it * NTHR;
            int row = idx >> 4, f = idx & 15;
            float4 v = *reinterpret_cast<const float4*>(smem + SM_X(s) + row * 256 + f * 16);
            uint32_t sw = swz((uint32_t)(row * 128 + f * 8));
            *reinterpret_cast<uint2*>(smem + SM_A16(s) + sw) =
                make_uint2(cvt2h(v.x, v.y), cvt2h(v.z, v.w));
        }
    };
    auto convertA_tail = [&](int s) {              // 16 valid cols only
        int row = tid >> 2, f = tid & 3;
        float4 v = *reinterpret_cast<const float4*>(smem + SM_X(s) + row * 256 + f * 16);
        uint32_t sw = swz((uint32_t)(row * 128 + f * 8));
        *reinterpret_cast<uint2*>(smem + SM_A16(s) + sw) =
            make_uint2(cvt2h(v.x, v.y), cvt2h(v.z, v.w));
    };
    auto computeKS = [&](int st, int sa2, int ks) {
        uint32_t b[8][2];
        #pragma unroll
        for (int p = 0; p < 4; ++p) {
            int n  = wn * 64 + p * 16 + ((g & 2) ? 8 : 0) + lr;
            int kk = ks * 16 + ((g & 1) ? 8 : 0);
            ldm_x4(b[2 * p][0], b[2 * p][1], b[2 * p + 1][0], b[2 * p + 1][1],
                   sb + SM_B(st) + swz((uint32_t)(n * 128 + kk * 2)));
        }
        uint32_t a[2][4];
        #pragma unroll
        for (int i = 0; i < 2; ++i) {
            int row = wm * 32 + i * 16 + ((g & 1) ? 8 : 0) + lr;
            int kk  = ks * 16 + ((g & 2) ? 8 : 0);
            ldm_x4(a[i][0], a[i][1], a[i][2], a[i][3],
                   sb + SM_A16(sa2) + swz((uint32_t)(row * 128 + kk * 2)));
        }
        #pragma unroll
        for (int i = 0; i < 2; ++i)
            #pragma unroll
            for (int j = 0; j < 8; ++j) mma16816(acc[i][j], a[i], b[j]);
    };

    // ---- prologue: groups X0 | B0 | X1 ----
    issueX(0, 0);
    issueB(0, 0);
    issueX(1, 1);
    asm volatile("cp.async.wait_group 2;" ::: "memory");   // X0 done
    convertA(0);
    asm volatile("cp.async.wait_group 1;" ::: "memory");   // B0 done (X1 pending)
    __syncthreads();

    // ---- mainloop: iter c consumes A16[c&1], B[c&1]; sa ring holds x(c+1) ----
    for (int c = 0; c < NCHUNK; ++c) {
        if (c + 1 < NCHUNK) {
            if (c + 1 == NCHUNK - 1) issueB_tail((c + 1) & 1);
            else                     issueB(c + 1, (c + 1) & 1);
        }
        if (c + 2 < NCHUNK) {
            if (c + 2 == NCHUNK - 1) issueX_tail((c + 2) & 1);
            else                     issueX(c + 2, (c + 2) & 1);
        }
        if (c == NCHUNK - 1) {
            computeKS(c & 1, c & 1, 0);            // trimmed tail: K=16, all warps
        } else {
            #pragma unroll
            for (int k = 0; k < 4; ++k)
                computeKS(c & 1, c & 1, (k + ks0) & 3);   // staggered by wm
        }
        if (c + 1 < NCHUNK) {
            if (c + 2 < NCHUNK)
                asm volatile("cp.async.wait_group 2;" ::: "memory");  // X(c+1) done
            else
                asm volatile("cp.async.wait_group 1;" ::: "memory");
            if (c + 1 == NCHUNK - 1) convertA_tail((c + 1) & 1);
            else                     convertA((c + 1) & 1);
            if (c + 2 < NCHUNK)
                asm volatile("cp.async.wait_group 1;" ::: "memory");  // B(c+1) done
            else
                asm volatile("cp.async.wait_group 0;" ::: "memory");
            __syncthreads();
        }
    }

    // ---- epilogue: out = relu(a1*acc) @ w2^T ----
    const float a1v = alpha1[0];
    #pragma unroll
    for (int i = 0; i < 2; ++i)
        #pragma unroll
        for (int j = 0; j < 8; ++j)
            #pragma unroll
            for (int r = 0; r < 4; ++r)
                acc[i][j][r] = fmaxf(a1v * acc[i][j][r], 0.0f);

    __syncthreads();                               // mainloop smem dead; alias
    for (int i = tid; i < OUT * HID; i += NTHR)
        reinterpret_cast<float*>(smem + SM_W2)[i] = g_w2f[i];
    __syncthreads();

    const float* w2s = reinterpret_cast<const float*>(smem + SM_W2);
    float* part = reinterpret_cast<float*>(smem + SM_PART);
    const int q = lane & 3, gq = lane >> 2;

    #pragma unroll
    for (int o = 0; o < OUT; ++o) {
        float w2v[8][2];
        #pragma unroll
        for (int j = 0; j < 8; ++j) {
            w2v[j][0] = w2s[o * HID + wn * 64 + j * 8 + q * 2];
            w2v[j][1] = w2s[o * HID + wn * 64 + j * 8 + q * 2 + 1];
        }
        #pragma unroll
        for (int i = 0; i < 2; ++i)
            #pragma unroll
            for (int h2 = 0; h2 < 2; ++h2) {
                float s = 0.0f;
                #pragma unroll
                for (int j = 0; j < 8; ++j)
                    s += acc[i][j][h2 * 2] * w2v[j][0] + acc[i][j][h2 * 2 + 1] * w2v[j][1];
                s += __shfl_xor_sync(0xffffffffu, s, 1);
                s += __shfl_xor_sync(0xffffffffu, s, 2);
                if (q == 0) {
                    int row = wm * 32 + i * 16 + h2 * 8 + gq;
                    part[wn * (BM * OUT) + row * OUT + o] = s;
                }
            }
    }
    __syncthreads();

    for (int idx = tid; idx < BM * OUT; idx += NTHR) {
        float v = part[idx] + part[BM * OUT + idx] +
                  part[2 * BM * OUT + idx] + part[3 * BM * OUT + idx];
        out[(size_t)bm * OUT + idx] = v;
    }
}

// ---------------------------------------------------------------------------
extern "C" void kernel_launch(void* const* d_in, const int* in_sizes, int n_in,
                              void* d_out, int out_size) {
    const float* x   = (const float*)d_in[0];
    const int*   w1p = (const int*)d_in[1];
    const int*   m1p = (const int*)d_in[2];
    const float* a1  = (const float*)d_in[3];
    const int*   w2p = (const int*)d_in[4];
    const int*   m2p = (const int*)d_in[5];
    const float* a2  = (const float*)d_in[6];
    float* out = (float*)d_out;

    cudaFuncSetAttribute(fused, cudaFuncAttributeMaxDynamicSharedMemorySize, SMEM_TOTAL);

    int total = HID * KPAD + OUT * HID;
    unpack_all<<<(total + 255) / 256, 256>>>(w1p, m1p, w2p, m2p, a2);
    fused<<<BATCH / BM, NTHR, SMEM_TOTAL>>>(x, a1, out);
}

// round 16
// speedup vs baseline: 1.9817x; 1.0314x over previous
#include <cuda_runtime.h>
#include <cuda_fp16.h>
#include <cstdint>

#define BATCH 32768
#define IN1   784
#define KPAD  832          // 13 * 64 (zero-padded)
#define HID   256
#define OUT   10
#define W1B   98
#define W2B   32
#define KC    64
#define NCHUNK 13
#define BM    64
#define NTHR  256

// -------- device scratch (allocation-free rule) --------
__device__ __align__(16) __half g_w1h[HID * KPAD];   // [256][832] fp16 {-1,0,+1}
__device__ float g_w2f[OUT * HID];                   // [10][256] fp32 (incl alpha2)

// -------- shared memory layout (bytes) --------
#define SM_X(s)   ((s) * 16384)            // x fp32 ring: 64 x 64 fp32 = 16KB x2
#define SM_A16(s) (32768 + (s) * 8192)     // A fp16: 64 x 64 = 8KB x2
#define SM_B(s)   (49152 + (s) * 32768)    // B fp16: 256 x 64 = 32KB x2
#define SM_W2     0                        // epilogue alias
#define SM_PART   16384                    // epilogue alias
#define SMEM_TOTAL 114688                  // 112KB -> 2 CTAs/SM

// -------- helpers --------
__device__ __forceinline__ uint32_t smem_u32(const void* p) {
    uint32_t a;
    asm("{ .reg .u64 t; cvta.to.shared.u64 t, %1; cvt.u32.u64 %0, t; }" : "=r"(a) : "l"(p));
    return a;
}
__device__ __forceinline__ uint32_t swz(uint32_t off) {  // SW128
    return off ^ ((off >> 3) & 0x70);
}
__device__ __forceinline__ uint32_t cvt2h(float lo, float hi) {  // -> {lo | hi<<16}
    uint32_t r;
    asm("cvt.rn.f16x2.f32 %0, %1, %2;" : "=r"(r) : "f"(hi), "f"(lo));
    return r;
}
__device__ __forceinline__ void ldm_x4(uint32_t& r0, uint32_t& r1, uint32_t& r2, uint32_t& r3,
                                       uint32_t addr) {
    asm volatile("ldmatrix.sync.aligned.m8n8.x4.shared.b16 {%0,%1,%2,%3}, [%4];"
                 : "=r"(r0), "=r"(r1), "=r"(r2), "=r"(r3) : "r"(addr));
}
__device__ __forceinline__ void mma16816(float* d, const uint32_t* a, const uint32_t* b) {
    asm volatile(
        "mma.sync.aligned.m16n8k16.row.col.f32.f16.f16.f32 "
        "{%0,%1,%2,%3}, {%4,%5,%6,%7}, {%8,%9}, {%0,%1,%2,%3};"
        : "+f"(d[0]), "+f"(d[1]), "+f"(d[2]), "+f"(d[3])
        : "r"(a[0]), "r"(a[1]), "r"(a[2]), "r"(a[3]), "r"(b[0]), "r"(b[1]));
}
__device__ __forceinline__ void cpa16(uint32_t dst, const void* src) {
    asm volatile("cp.async.cg.shared.global [%0], [%1], 16;" :: "r"(dst), "l"(src) : "memory");
}
__device__ __forceinline__ void cpcommit() {
    asm volatile("cp.async.commit_group;" ::: "memory");
}

// ---------------------------------------------------------------------------
__global__ void unpack_all(const int* __restrict__ w1p, const int* __restrict__ m1p,
                           const int* __restrict__ w2p, const int* __restrict__ m2p,
                           const float* __restrict__ a2) {
    int idx = blockIdx.x * 256 + threadIdx.x;
    if (idx < HID * KPAD) {
        int o = idx / KPAD, i = idx - o * KPAD;
        float v = 0.0f;
        if (i < IN1) {
            int sh = 7 - (i & 7);
            int wb = (w1p[o * W1B + (i >> 3)] >> sh) & 1;
            int mb = (m1p[o * W1B + (i >> 3)] >> sh) & 1;
            v = (2.0f * (float)wb - 1.0f) * (float)mb;
        }
        g_w1h[idx] = __float2half_rn(v);
    } else {
        int j = idx - HID * KPAD;
        if (j < OUT * HID) {
            int o = j / HID, i = j - o * HID;
            int sh = 7 - (i & 7);
            int wb = (w2p[o * W2B + (i >> 3)] >> sh) & 1;
            int mb = (m2p[o * W2B + (i >> 3)] >> sh) & 1;
            g_w2f[j] = (2.0f * (float)wb - 1.0f) * (float)mb * a2[0];
        }
    }
}

// ---------------------------------------------------------------------------
// Fused, 2 CTAs/SM. Round-9 data choreography; convert(c+1) hoisted to the
// HEAD of iteration c (off the barrier-critical tail).
// ---------------------------------------------------------------------------
__global__ void __launch_bounds__(NTHR, 2)
fused(const float* __restrict__ x, const float* __restrict__ alpha1,
      float* __restrict__ out) {
    extern __shared__ char smem[];
    const uint32_t sb = smem_u32(smem);
    const int tid = threadIdx.x, wid = tid >> 5, lane = tid & 31;
    const int wm = wid >> 2, wn = wid & 3;        // 2x4 warp grid, 32x64 warp tiles
    const int bm = blockIdx.x * BM;
    const float* __restrict__ xb = x + (size_t)bm * IN1;

    float acc[2][8][4];
    #pragma unroll
    for (int i = 0; i < 2; ++i)
        #pragma unroll
        for (int j = 0; j < 8; ++j)
            #pragma unroll
            for (int r = 0; r < 4; ++r) acc[i][j][r] = 0.0f;

    const int g = lane >> 3, lr = lane & 7;

    // ---- async issue helpers ----
    auto issueX = [&](int c, int s) {              // 1024 granules, 4/thread
        const int kt = c * KC;
        #pragma unroll
        for (int it = 0; it < 4; ++it) {
            int idx = tid + it * NTHR;
            int row = idx >> 4, f = idx & 15;
            cpa16(sb + SM_X(s) + (uint32_t)(row * 256 + f * 16),
                  xb + (size_t)row * IN1 + kt + f * 4);
        }
        cpcommit();
    };
    auto issueX_tail = [&](int s) {                // chunk 12: cols 768..783 (f<4)
        int row = tid >> 2, f = tid & 3;
        cpa16(sb + SM_X(s) + (uint32_t)(row * 256 + f * 16),
              xb + (size_t)row * IN1 + 768 + f * 4);
        cpcommit();
    };
    auto issueB = [&](int c, int s) {              // 2048 granules, 8/thread
        const int kt = c * KC;
        #pragma unroll
        for (int it = 0; it < 8; ++it) {
            int idx = tid + it * NTHR;
            int n = idx >> 3, u = idx & 7;
            cpa16(sb + SM_B(s) + swz((uint32_t)(n * 128 + u * 16)),
                  g_w1h + (size_t)n * KPAD + kt + u * 8);
        }
        cpcommit();
    };
    auto issueB_tail = [&](int s) {                // only u<2 (valid 16 cols)
        #pragma unroll
        for (int it = 0; it < 2; ++it) {
            int idx = tid + it * NTHR;
            int n = idx >> 1, u = idx & 1;
            cpa16(sb + SM_B(s) + swz((uint32_t)(n * 128 + u * 16)),
                  g_w1h + (size_t)n * KPAD + 768 + u * 8);
        }
        cpcommit();
    };
    // ---- fp32 smem -> fp16 smem conversion (round-9 verbatim) ----
    auto convertA = [&](int s) {
        #pragma unroll
        for (int it = 0; it < 4; ++it) {
            int idx = tid + it * NTHR;
            int row = idx >> 4, f = idx & 15;
            float4 v = *reinterpret_cast<const float4*>(smem + SM_X(s) + row * 256 + f * 16);
            uint32_t sw = swz((uint32_t)(row * 128 + f * 8));
            *reinterpret_cast<uint2*>(smem + SM_A16(s) + sw) =
                make_uint2(cvt2h(v.x, v.y), cvt2h(v.z, v.w));
        }
    };
    auto convertA_tail = [&](int s) {              // 16 valid cols only
        int row = tid >> 2, f = tid & 3;
        float4 v = *reinterpret_cast<const float4*>(smem + SM_X(s) + row * 256 + f * 16);
        uint32_t sw = swz((uint32_t)(row * 128 + f * 8));
        *reinterpret_cast<uint2*>(smem + SM_A16(s) + sw) =
            make_uint2(cvt2h(v.x, v.y), cvt2h(v.z, v.w));
    };
    auto computeKS = [&](int st, int sa2, int ks) {
        uint32_t b[8][2];
        #pragma unroll
        for (int p = 0; p < 4; ++p) {
            int n  = wn * 64 + p * 16 + ((g & 2) ? 8 : 0) + lr;
            int kk = ks * 16 + ((g & 1) ? 8 : 0);
            ldm_x4(b[2 * p][0], b[2 * p][1], b[2 * p + 1][0], b[2 * p + 1][1],
                   sb + SM_B(st) + swz((uint32_t)(n * 128 + kk * 2)));
        }
        uint32_t a[2][4];
        #pragma unroll
        for (int i = 0; i < 2; ++i) {
            int row = wm * 32 + i * 16 + ((g & 1) ? 8 : 0) + lr;
            int kk  = ks * 16 + ((g & 2) ? 8 : 0);
            ldm_x4(a[i][0], a[i][1], a[i][2], a[i][3],
                   sb + SM_A16(sa2) + swz((uint32_t)(row * 128 + kk * 2)));
        }
        #pragma unroll
        for (int i = 0; i < 2; ++i)
            #pragma unroll
            for (int j = 0; j < 8; ++j) mma16816(acc[i][j], a[i], b[j]);
    };

    // ---- prologue: commits X0 | B0 | X1 ----
    issueX(0, 0);
    issueB(0, 0);
    issueX(1, 1);
    asm volatile("cp.async.wait_group 2;" ::: "memory");   // X0 done
    convertA(0);
    asm volatile("cp.async.wait_group 1;" ::: "memory");   // B0 done (X1 pending)
    __syncthreads();

    // ---- mainloop: entry pending = [X(c+1)] ----
    for (int c = 0; c < NCHUNK; ++c) {
        // HEAD: convert next A tile (X(c+1) issued last iter; long covered)
        if (c + 1 < NCHUNK) {
            asm volatile("cp.async.wait_group 0;" ::: "memory");      // X(c+1) done
            if (c + 1 == NCHUNK - 1) convertA_tail((c + 1) & 1);
            else                     convertA((c + 1) & 1);
        }
        if (c + 1 < NCHUNK) {
            if (c + 1 == NCHUNK - 1) issueB_tail((c + 1) & 1);
            else                     issueB(c + 1, (c + 1) & 1);
        }
        if (c + 2 < NCHUNK) {
            if (c + 2 == NCHUNK - 1) issueX_tail((c + 2) & 1);
            else                     issueX(c + 2, (c + 2) & 1);
        }
        if (c == NCHUNK - 1) {
            computeKS(c & 1, c & 1, 0);            // trimmed tail: K=16
        } else {
            #pragma unroll
            for (int ks = 0; ks < 4; ++ks) computeKS(c & 1, c & 1, ks);
        }
        // TAIL: just B(c+1) + barrier
        if (c + 1 < NCHUNK) {
            if (c + 2 < NCHUNK)
                asm volatile("cp.async.wait_group 1;" ::: "memory");  // B(c+1) done
            else
                asm volatile("cp.async.wait_group 0;" ::: "memory");
            __syncthreads();
        }
    }

    // ---- epilogue: out = relu(a1*acc) @ w2^T ----
    const float a1v = alpha1[0];
    #pragma unroll
    for (int i = 0; i < 2; ++i)
        #pragma unroll
        for (int j = 0; j < 8; ++j)
            #pragma unroll
            for (int r = 0; r < 4; ++r)
                acc[i][j][r] = fmaxf(a1v * acc[i][j][r], 0.0f);

    __syncthreads();                               // mainloop smem dead; alias
    for (int i = tid; i < OUT * HID; i += NTHR)
        reinterpret_cast<float*>(smem + SM_W2)[i] = g_w2f[i];
    __syncthreads();

    const float* w2s = reinterpret_cast<const float*>(smem + SM_W2);
    float* part = reinterpret_cast<float*>(smem + SM_PART);
    const int q = lane & 3, gq = lane >> 2;

    #pragma unroll
    for (int o = 0; o < OUT; ++o) {
        float w2v[8][2];
        #pragma unroll
        for (int j = 0; j < 8; ++j) {
            w2v[j][0] = w2s[o * HID + wn * 64 + j * 8 + q * 2];
            w2v[j][1] = w2s[o * HID + wn * 64 + j * 8 + q * 2 + 1];
        }
        #pragma unroll
        for (int i = 0; i < 2; ++i)
            #pragma unroll
            for (int h2 = 0; h2 < 2; ++h2) {
                float s = 0.0f;
                #pragma unroll
                for (int j = 0; j < 8; ++j)
                    s += acc[i][j][h2 * 2] * w2v[j][0] + acc[i][j][h2 * 2 + 1] * w2v[j][1];
                s += __shfl_xor_sync(0xffffffffu, s, 1);
                s += __shfl_xor_sync(0xffffffffu, s, 2);
                if (q == 0) {
                    int row = wm * 32 + i * 16 + h2 * 8 + gq;
                    part[wn * (BM * OUT) + row * OUT + o] = s;
                }
            }
    }
    __syncthreads();

    for (int idx = tid; idx < BM * OUT; idx += NTHR) {
        float v = part[idx] + part[BM * OUT + idx] +
                  part[2 * BM * OUT + idx] + part[3 * BM * OUT + idx];
        out[(size_t)bm * OUT + idx] = v;
    }
}

// ---------------------------------------------------------------------------
extern "C" void kernel_launch(void* const* d_in, const int* in_sizes, int n_in,
                              void* d_out, int out_size) {
    const float* x   = (const float*)d_in[0];
    const int*   w1p = (const int*)d_in[1];
    const int*   m1p = (const int*)d_in[2];
    const float* a1  = (const float*)d_in[3];
    const int*   w2p = (const int*)d_in[4];
    const int*   m2p = (const int*)d_in[5];
    const float* a2  = (const float*)d_in[6];
    float* out = (float*)d_out;

    cudaFuncSetAttribute(fused, cudaFuncAttributeMaxDynamicSharedMemorySize, SMEM_TOTAL);

    int total = HID * KPAD + OUT * HID;
    unpack_all<<<(total + 255) / 256, 256>>>(w1p, m1p, w2p, m2p, a2);
    fused<<<BATCH / BM, NTHR, SMEM_TOTAL>>>(x, a1, out);
}